// round 1
// baseline (speedup 1.0000x reference)
#include <cuda_runtime.h>
#include <math.h>

// Problem constants
#define Bb   8
#define Cc   1536
#define Tt   4096
#define Aa   128
#define K3C  4608          // 3*C
#define EPSF 1e-12f

// ---------------- scratch (device globals; no allocation allowed) ----------------
__device__ float g_mean[(size_t)Bb * Cc * Tt];   // 192 MB
__device__ float g_std [(size_t)Bb * Cc * Tt];   // 192 MB
__device__ float g_W1t [K3C * Aa];               // transposed W1: [k][a]
__device__ float g_logits[Bb * Tt];
__device__ float g_e     [Bb * Tt];
__device__ float g_Z     [Bb * Tt];

// ---------------- helpers ----------------

// lengths may arrive as int64 or int32 depending on jax x64 config.
// lengths are in [T/2, T] = [2048,4096], so word[1]==0  <=>  int64 layout.
__device__ __forceinline__ int load_len(const int* __restrict__ L, int b) {
    return (L[1] == 0) ? L[2 * b] : L[b];
}

// inclusive Kogge-Stone scan of 256 floats in shared memory
__device__ __forceinline__ void scan256(float* buf, int tid) {
    #pragma unroll
    for (int off = 1; off < 256; off <<= 1) {
        float a = 0.f;
        if (tid >= off) a = buf[tid - off];
        __syncthreads();
        buf[tid] += a;
        __syncthreads();
    }
}

// ---------------- K0: transpose W1 (A,3C) -> (3C,A), L2-resident for the GEMM ----------------
__global__ __launch_bounds__(256) void k_transpose(const float* __restrict__ W1) {
    int idx = blockIdx.x * 256 + threadIdx.x;
    if (idx < K3C * Aa) {
        int k = idx >> 7;      // /128
        int a = idx & 127;
        g_W1t[idx] = W1[(size_t)a * K3C + k];
    }
}

// ---------------- K1: causal mean/std per (b,c) row ----------------
__global__ __launch_bounds__(256) void k_scan_stats(const float* __restrict__ x,
                                                    const int* __restrict__ L) {
    int row = blockIdx.x;               // b*C + c
    int b = row / Cc;
    int len = load_len(L, b);

    __shared__ float xs[Tt];
    __shared__ float ss[Tt];
    __shared__ float s1w[256], s2w[256];

    int tid = threadIdx.x;
    const float* xr = x + (size_t)row * Tt;
    for (int j = tid; j < Tt; j += 256) xs[j] = xr[j];
    __syncthreads();

    int base = tid * 16;
    float s1 = 0.f, s2 = 0.f;
    #pragma unroll
    for (int k = 0; k < 16; k++) {
        int t = base + k;
        float v = (t < len) ? xs[t] : 0.f;
        s1 += v; s2 += v * v;
    }
    s1w[tid] = s1; s2w[tid] = s2;
    __syncthreads();

    // fused 2-array scan
    #pragma unroll
    for (int off = 1; off < 256; off <<= 1) {
        float a1 = 0.f, a2 = 0.f;
        if (tid >= off) { a1 = s1w[tid - off]; a2 = s2w[tid - off]; }
        __syncthreads();
        s1w[tid] += a1; s2w[tid] += a2;
        __syncthreads();
    }

    float p1 = tid ? s1w[tid - 1] : 0.f;
    float p2 = tid ? s2w[tid - 1] : 0.f;
    #pragma unroll
    for (int k = 0; k < 16; k++) {
        int t = base + k;
        float xv = xs[t];
        float v  = (t < len) ? xv : 0.f;
        p1 += v; p2 += v * v;
        int cn = min(t + 1, len); if (cn < 1) cn = 1;
        float cnf = (float)cn;
        float m   = p1 / cnf;
        float var = p2 / cnf - m * m;
        xs[t] = m;
        ss[t] = sqrtf(fmaxf(var, EPSF));
    }
    __syncthreads();

    float* mr = g_mean + (size_t)row * Tt;
    float* sr = g_std  + (size_t)row * Tt;
    for (int j = tid; j < Tt; j += 256) { mr[j] = xs[j]; sr[j] = ss[j]; }
}

// ---------------- K2: fused GEMM (attn_in @ W1^T) + tanh + W2 reduction -> logits ----------------
// A-matrix: attn_in[b, t, k], k<C -> x, k<2C -> mean, else std. Stored channel-major (stride T).
// Tile: BM=64 (t), BN=128 (a, full), BK=32. 256 threads, 4x8 outputs each.
#define GBM 64
#define GBK 32
__global__ __launch_bounds__(256) void k_gemm(const float* __restrict__ x,
                                              const float* __restrict__ b1,
                                              const float* __restrict__ W2) {
    int b  = blockIdx.y;
    int t0 = blockIdx.x * GBM;

    __shared__ float As[GBK][GBM];    // 8 KB
    __shared__ float Bs[GBK][Aa];     // 16 KB

    int tid = threadIdx.x;
    int tx = tid & 15;                // a-group (16 groups x 8)
    int ty = tid >> 4;                // t-group (16 groups x 4)

    // loader indices
    int l_k  = tid >> 3;              // 0..31
    int l_t  = (tid & 7) * 8;         // 8 consecutive t per thread
    int l_a  = (tid & 7) * 16;        // 16 consecutive a per thread

    float acc[4][8] = {};

    for (int k0 = 0; k0 < K3C; k0 += GBK) {
        int region = k0 / Cc;                         // 0,1,2 (chunk never straddles)
        const float* buf = (region == 0) ? x : (region == 1) ? g_mean : g_std;
        int cbase = k0 - region * Cc;

        // load A tile: 32 k-rows x 64 t
        {
            const float* src = buf + ((size_t)(b * Cc + cbase + l_k)) * Tt + t0 + l_t;
            float4 v0 = *(const float4*)(src);
            float4 v1 = *(const float4*)(src + 4);
            *(float4*)&As[l_k][l_t]     = v0;
            *(float4*)&As[l_k][l_t + 4] = v1;
        }
        // load B tile: W1t[(k0+kl)*128 + a]
        {
            const float4* src = (const float4*)(g_W1t + (size_t)(k0 + l_k) * Aa + l_a);
            float4* dst = (float4*)&Bs[l_k][l_a];
            #pragma unroll
            for (int i = 0; i < 4; i++) dst[i] = src[i];
        }
        __syncthreads();

        #pragma unroll
        for (int kk = 0; kk < GBK; kk++) {
            float4 ra4 = *(const float4*)&As[kk][ty * 4];
            float4 rb0 = *(const float4*)&Bs[kk][tx * 8];
            float4 rb1 = *(const float4*)&Bs[kk][tx * 8 + 4];
            float ra[4] = {ra4.x, ra4.y, ra4.z, ra4.w};
            float rb[8] = {rb0.x, rb0.y, rb0.z, rb0.w, rb1.x, rb1.y, rb1.z, rb1.w};
            #pragma unroll
            for (int i = 0; i < 4; i++)
                #pragma unroll
                for (int j = 0; j < 8; j++)
                    acc[i][j] += ra[i] * rb[j];
        }
        __syncthreads();
    }

    // epilogue: tanh + dot with W2 (b2 is a per-row constant, cancels in softmax)
    float part[4];
    #pragma unroll
    for (int i = 0; i < 4; i++) {
        float s = 0.f;
        #pragma unroll
        for (int j = 0; j < 8; j++) {
            int a = tx * 8 + j;
            float h = tanhf(acc[i][j] + __ldg(&b1[a]));
            s += h * __ldg(&W2[a]);
        }
        part[i] = s;
    }
    // reduce over the 16 tx lanes (each half-warp holds one t-group pair)
    #pragma unroll
    for (int i = 0; i < 4; i++) {
        float s = part[i];
        #pragma unroll
        for (int off = 1; off < 16; off <<= 1)
            s += __shfl_xor_sync(0xFFFFFFFF, s, off);
        part[i] = s;
    }
    if (tx == 0) {
        #pragma unroll
        for (int i = 0; i < 4; i++)
            g_logits[(size_t)b * Tt + t0 + ty * 4 + i] = part[i];
    }
}

// ---------------- K3: per-batch max, exp, cumsum -> e, Z ----------------
__global__ __launch_bounds__(256) void k_softmax() {
    int b = blockIdx.x;
    __shared__ float sm[Tt];
    __shared__ float red[256];
    int tid = threadIdx.x;

    const float* lr = g_logits + b * Tt;
    float mx = -INFINITY;
    for (int j = tid; j < Tt; j += 256) { float v = lr[j]; sm[j] = v; mx = fmaxf(mx, v); }
    red[tid] = mx;
    __syncthreads();
    for (int off = 128; off; off >>= 1) {
        if (tid < off) red[tid] = fmaxf(red[tid], red[tid + off]);
        __syncthreads();
    }
    float M = red[0];
    __syncthreads();

    int base = tid * 16;
    float s = 0.f;
    #pragma unroll
    for (int k = 0; k < 16; k++) {
        float ev = expf(sm[base + k] - M);
        sm[base + k] = ev;
        s += ev;
    }
    red[tid] = s;
    __syncthreads();
    scan256(red, tid);

    float p = tid ? red[tid - 1] : 0.f;
    #pragma unroll
    for (int k = 0; k < 16; k++) {
        int t = base + k;
        float ev = sm[t];
        p += ev;
        g_e[b * Tt + t] = ev;
        g_Z[b * Tt + t] = p;
    }
}

// ---------------- K4: weighted mean/std scans + final reduction ----------------
__global__ __launch_bounds__(256) void k_weighted(const float* __restrict__ x,
                                                  float* __restrict__ out) {
    int row = blockIdx.x;
    int b = row / Cc;
    int c = row - b * Cc;

    __shared__ float xs[Tt];
    __shared__ float es[Tt];
    __shared__ float w1s[256], w2s[256];

    int tid = threadIdx.x;
    const float* xr = x + (size_t)row * Tt;
    const float* er = g_e + b * Tt;
    const float* zr = g_Z + b * Tt;
    for (int j = tid; j < Tt; j += 256) { xs[j] = xr[j]; es[j] = er[j]; }
    __syncthreads();

    int base = tid * 16;

    // scan 1: P = cumsum(e*x); wm = P/Z; v = e*(x-wm)^2 (stored in xs)
    float s = 0.f;
    #pragma unroll
    for (int k = 0; k < 16; k++) { int t = base + k; s += es[t] * xs[t]; }
    w1s[tid] = s;
    __syncthreads();
    scan256(w1s, tid);

    float p = tid ? w1s[tid - 1] : 0.f;
    float sum_wm = 0.f, s2 = 0.f;
    #pragma unroll
    for (int k = 0; k < 16; k++) {
        int t = base + k;
        p += es[t] * xs[t];
        float wm = p / zr[t];
        sum_wm += wm;
        float d = xs[t] - wm;
        float v = es[t] * d * d;
        xs[t] = v;
        s2 += v;
    }
    __syncthreads();   // protect w1s prefix reads before reuse

    // scan 2: Q = cumsum(v); wstd = sqrt(clip(Q/Z, EPS))
    w1s[tid] = s2;
    __syncthreads();
    scan256(w1s, tid);

    float q = tid ? w1s[tid - 1] : 0.f;
    float sum_ws = 0.f;
    #pragma unroll
    for (int k = 0; k < 16; k++) {
        int t = base + k;
        q += xs[t];
        float wv = q / zr[t];
        sum_ws += sqrtf(fmaxf(wv, EPSF));
    }
    __syncthreads();   // protect w1s prefix reads before reuse as reduce buffer

    w1s[tid] = sum_wm;
    w2s[tid] = sum_ws;
    __syncthreads();
    for (int off = 128; off; off >>= 1) {
        if (tid < off) { w1s[tid] += w1s[tid + off]; w2s[tid] += w2s[tid + off]; }
        __syncthreads();
    }
    if (tid == 0) {
        const float FW = (float)(1.0 / (4096.0 + 1e-12));
        out[(size_t)b * 2 * Cc + c]      = w1s[0] * FW;
        out[(size_t)b * 2 * Cc + Cc + c] = w2s[0] * FW;
    }
}

// ---------------- launch ----------------
extern "C" void kernel_launch(void* const* d_in, const int* in_sizes, int n_in,
                              void* d_out, int out_size) {
    (void)in_sizes; (void)n_in; (void)out_size;
    const float* x  = (const float*)d_in[0];
    const int*   L  = (const int*)  d_in[1];   // int64 or int32, detected in-kernel
    const float* W1 = (const float*)d_in[2];
    const float* b1 = (const float*)d_in[3];
    const float* W2 = (const float*)d_in[4];
    // d_in[5] = b2: a per-row constant on logits; cancels exactly in softmax.
    float* out = (float*)d_out;

    k_transpose<<<(K3C * Aa + 255) / 256, 256>>>(W1);
    k_scan_stats<<<Bb * Cc, 256>>>(x, L);
    dim3 g2(Tt / GBM, Bb);
    k_gemm<<<g2, 256>>>(x, b1, W2);
    k_softmax<<<Bb, 256>>>();
    k_weighted<<<Bb * Cc, 256>>>(x, out);
}

// round 3
// speedup vs baseline: 1.8688x; 1.8688x over previous
#include <cuda_runtime.h>
#include <cuda_bf16.h>
#include <cstdint>
#include <math.h>

// Problem constants
#define Bb   8
#define Cc   1536
#define Tt   4096
#define Aa   128
#define K3C  4608          // 3*C
#define EPSF 1e-12f

// ---------------- scratch (device globals; no allocation allowed) ----------------
__device__ __nv_bfloat16 g_mh[(size_t)Bb * Cc * Tt];   // mean hi (96MB)
__device__ __nv_bfloat16 g_ml[(size_t)Bb * Cc * Tt];   // mean lo
__device__ __nv_bfloat16 g_sh[(size_t)Bb * Cc * Tt];   // std hi
__device__ __nv_bfloat16 g_sl[(size_t)Bb * Cc * Tt];   // std lo
__device__ __nv_bfloat16 g_W1h[Aa * K3C];
__device__ __nv_bfloat16 g_W1l[Aa * K3C];
__device__ float g_logits[Bb * Tt];
__device__ float g_e     [Bb * Tt];
__device__ float g_Z     [Bb * Tt];

// ---------------- helpers ----------------
__device__ __forceinline__ uint32_t smem_u32(const void* p) {
    uint32_t a;
    asm("{ .reg .u64 t; cvta.to.shared.u64 t, %1; cvt.u32.u64 %0, t; }" : "=r"(a) : "l"(p));
    return a;
}
__device__ __forceinline__ int load_len(const int* __restrict__ L, int b) {
    return (L[1] == 0) ? L[2 * b] : L[b];   // int64 vs int32 detection
}
__device__ __forceinline__ void scan256(float* buf, int tid) {
    #pragma unroll
    for (int off = 1; off < 256; off <<= 1) {
        float a = 0.f;
        if (tid >= off) a = buf[tid - off];
        __syncthreads();
        buf[tid] += a;
        __syncthreads();
    }
}
__device__ __forceinline__ void split_bf16(float v, __nv_bfloat16& h, __nv_bfloat16& l) {
    h = __float2bfloat16_rn(v);
    l = __float2bfloat16_rn(v - __bfloat162float(h));
}
__device__ __forceinline__ float fast_tanh(float v) {
    float e = __expf(2.f * v);          // inf-safe: e=inf -> 1, e=0 -> -1
    return 1.f - 2.f / (e + 1.f);
}

// ldmatrix wrappers
__device__ __forceinline__ void ldsm_x4(uint32_t& r0, uint32_t& r1, uint32_t& r2, uint32_t& r3, uint32_t a) {
    asm volatile("ldmatrix.sync.aligned.m8n8.x4.shared.b16 {%0,%1,%2,%3}, [%4];"
                 : "=r"(r0), "=r"(r1), "=r"(r2), "=r"(r3) : "r"(a));
}
__device__ __forceinline__ void ldsm_x4_t(uint32_t& r0, uint32_t& r1, uint32_t& r2, uint32_t& r3, uint32_t a) {
    asm volatile("ldmatrix.sync.aligned.m8n8.x4.trans.shared.b16 {%0,%1,%2,%3}, [%4];"
                 : "=r"(r0), "=r"(r1), "=r"(r2), "=r"(r3) : "r"(a));
}
__device__ __forceinline__ void mma_bf16(float* d, const uint32_t* a, const uint32_t* b) {
    asm volatile(
        "mma.sync.aligned.m16n8k16.row.col.f32.bf16.bf16.f32 "
        "{%0,%1,%2,%3},{%4,%5,%6,%7},{%8,%9},{%0,%1,%2,%3};"
        : "+f"(d[0]), "+f"(d[1]), "+f"(d[2]), "+f"(d[3])
        : "r"(a[0]), "r"(a[1]), "r"(a[2]), "r"(a[3]), "r"(b[0]), "r"(b[1]));
}

// ---------------- K0: W1 -> bf16 hi/lo ----------------
__global__ __launch_bounds__(256) void k_prepW(const float* __restrict__ W1) {
    int i = blockIdx.x * 256 + threadIdx.x;
    if (i < Aa * K3C) {
        __nv_bfloat16 h, l;
        split_bf16(W1[i], h, l);
        g_W1h[i] = h; g_W1l[i] = l;
    }
}

// ---------------- K1: causal mean/std -> bf16 hi/lo ----------------
__global__ __launch_bounds__(256) void k_scan_stats(const float* __restrict__ x,
                                                    const int* __restrict__ L) {
    int row = blockIdx.x;               // b*C + c
    int b = row / Cc;
    int len = load_len(L, b);

    __shared__ float xs[Tt];
    __shared__ float ss[Tt];
    __shared__ float s1w[256], s2w[256];

    int tid = threadIdx.x;
    const float* xr = x + (size_t)row * Tt;
    for (int j = tid; j < Tt; j += 256) xs[j] = xr[j];
    __syncthreads();

    int base = tid * 16;
    float s1 = 0.f, s2 = 0.f;
    #pragma unroll
    for (int k = 0; k < 16; k++) {
        int t = base + k;
        float v = (t < len) ? xs[t] : 0.f;
        s1 += v; s2 += v * v;
    }
    s1w[tid] = s1; s2w[tid] = s2;
    __syncthreads();
    #pragma unroll
    for (int off = 1; off < 256; off <<= 1) {
        float a1 = 0.f, a2 = 0.f;
        if (tid >= off) { a1 = s1w[tid - off]; a2 = s2w[tid - off]; }
        __syncthreads();
        s1w[tid] += a1; s2w[tid] += a2;
        __syncthreads();
    }

    float p1 = tid ? s1w[tid - 1] : 0.f;
    float p2 = tid ? s2w[tid - 1] : 0.f;
    #pragma unroll
    for (int k = 0; k < 16; k++) {
        int t = base + k;
        float xv = xs[t];
        float v  = (t < len) ? xv : 0.f;
        p1 += v; p2 += v * v;
        int cn = min(t + 1, len); if (cn < 1) cn = 1;
        float cnf = (float)cn;
        float m   = p1 / cnf;
        float var = p2 / cnf - m * m;
        xs[t] = m;
        ss[t] = sqrtf(fmaxf(var, EPSF));
    }
    __syncthreads();

    size_t gb = (size_t)row * Tt;
    for (int j = tid; j < Tt; j += 256) {
        __nv_bfloat16 h, l;
        split_bf16(xs[j], h, l); g_mh[gb + j] = h; g_ml[gb + j] = l;
        split_bf16(ss[j], h, l); g_sh[gb + j] = h; g_sl[gb + j] = l;
    }
}

// ---------------- K2: bf16 mma.sync GEMM + tanh + W2 reduce -> logits ----------------
// logits[b,t] = sum_a W2[a] * tanh( sum_k attn[b,t,k] W1[a,k] + b1[a] )   (b2 cancels)
// A operand (m=t): attn tile stored [k][t] (natural), fragments via ldmatrix.x4.trans
// B operand (n=a): W1 [a][k] (natural k-contig), fragments via ldmatrix.x4
// hi/lo error-compensated split: acc += Ah*Bh + Al*Bh + Ah*Bl
#define BM 128
#define BK 32
#define APITCH 272          // bytes per k-row (128 t * 2B + 16 pad): 17 chunks, conflict-free
#define BPITCH 80           // bytes per a-row (32 k * 2B + 16 pad): 5 chunks, conflict-free

__global__ __launch_bounds__(256) void k_gemm_mma(const float* __restrict__ x,
                                                  const float* __restrict__ b1,
                                                  const float* __restrict__ W2) {
    __shared__ __align__(16) char sAh[BK * APITCH];    // 8704
    __shared__ __align__(16) char sAl[BK * APITCH];
    __shared__ __align__(16) char sBh[Aa * BPITCH];    // 10240
    __shared__ __align__(16) char sBl[Aa * BPITCH];
    __shared__ float red[2][BM];

    int tid = threadIdx.x;
    int wid = tid >> 5, lid = tid & 31;
    int wm = wid & 3;          // 4 m-warps * 32 t
    int wn = wid >> 2;         // 2 n-warps * 64 a
    int b  = blockIdx.y, t0 = blockIdx.x * BM;

    // loader indices
    int lr  = tid >> 3;        // A: k-row 0..31
    int ltc = tid & 7;         // A: 16-t chunk
    int la  = tid >> 1;        // B: a-row 0..127
    int lh  = tid & 1;         // B: k-half (16 k)

    uint32_t uAh = smem_u32(sAh), uAl = smem_u32(sAl);
    uint32_t uBh = smem_u32(sBh), uBl = smem_u32(sBl);

    // ldmatrix lane addressing (constant offsets per lane)
    int a_row_off = (lid & 7) + ((lid >> 4) << 3);            // k within 16-block
    int a_t_off   = wm * 32 + ((lid >> 3) & 1) * 8;           // t within warp tile (+ mf*16)
    int b_row     = wn * 64 + (lid & 7) + ((lid >> 4) << 3);  // a row (+ nb2*16)
    int b_k_off   = ((lid >> 3) & 1) * 8;                     // k within 16-block (+ s*16)

    float acc[2][8][4];
    #pragma unroll
    for (int i = 0; i < 2; i++)
        #pragma unroll
        for (int j = 0; j < 8; j++)
            #pragma unroll
            for (int q = 0; q < 4; q++) acc[i][j][q] = 0.f;

    for (int k0 = 0; k0 < K3C; k0 += BK) {
        int region = k0 / Cc;            // 0:x  1:mean  2:std (BK=32 never straddles)
        int cb = k0 - region * Cc;

        // ---- A tile: 32 k-rows x 128 t, hi+lo
        if (region == 0) {
            const float* src = x + ((size_t)(b * Cc + cb + lr)) * Tt + t0 + ltc * 16;
            float4 v[4];
            #pragma unroll
            for (int i = 0; i < 4; i++) v[i] = *(const float4*)(src + i * 4);
            uint32_t hp[8], lp[8];
            const float* vf = (const float*)v;
            #pragma unroll
            for (int j = 0; j < 8; j++) {
                __nv_bfloat16 h0, l0, h1, l1;
                split_bf16(vf[2*j],   h0, l0);
                split_bf16(vf[2*j+1], h1, l1);
                hp[j] = (uint32_t)__bfloat16_as_ushort(h0) | ((uint32_t)__bfloat16_as_ushort(h1) << 16);
                lp[j] = (uint32_t)__bfloat16_as_ushort(l0) | ((uint32_t)__bfloat16_as_ushort(l1) << 16);
            }
            char* dh = sAh + lr * APITCH + ltc * 32;
            char* dl = sAl + lr * APITCH + ltc * 32;
            ((uint4*)dh)[0] = make_uint4(hp[0], hp[1], hp[2], hp[3]);
            ((uint4*)dh)[1] = make_uint4(hp[4], hp[5], hp[6], hp[7]);
            ((uint4*)dl)[0] = make_uint4(lp[0], lp[1], lp[2], lp[3]);
            ((uint4*)dl)[1] = make_uint4(lp[4], lp[5], lp[6], lp[7]);
        } else {
            const __nv_bfloat16* srcH = (region == 1) ? g_mh : g_sh;
            const __nv_bfloat16* srcL = (region == 1) ? g_ml : g_sl;
            size_t g = ((size_t)(b * Cc + cb + lr)) * Tt + t0 + ltc * 16;
            char* dh = sAh + lr * APITCH + ltc * 32;
            char* dl = sAl + lr * APITCH + ltc * 32;
            ((float4*)dh)[0] = *(const float4*)(srcH + g);
            ((float4*)dh)[1] = *(const float4*)(srcH + g + 8);
            ((float4*)dl)[0] = *(const float4*)(srcL + g);
            ((float4*)dl)[1] = *(const float4*)(srcL + g + 8);
        }
        // ---- B tile: 128 a-rows x 32 k, hi+lo
        {
            size_t g = (size_t)la * K3C + k0 + lh * 16;
            char* dh = sBh + la * BPITCH + lh * 32;
            char* dl = sBl + la * BPITCH + lh * 32;
            ((float4*)dh)[0] = *(const float4*)(g_W1h + g);
            ((float4*)dh)[1] = *(const float4*)(g_W1h + g + 8);
            ((float4*)dl)[0] = *(const float4*)(g_W1l + g);
            ((float4*)dl)[1] = *(const float4*)(g_W1l + g + 8);
        }
        __syncthreads();

        #pragma unroll
        for (int s = 0; s < 2; s++) {                 // two k16 steps
            uint32_t ah[2][4], al[2][4];
            #pragma unroll
            for (int mf = 0; mf < 2; mf++) {
                uint32_t addr = (s * 16 + a_row_off) * APITCH + (a_t_off + mf * 16) * 2;
                ldsm_x4_t(ah[mf][0], ah[mf][1], ah[mf][2], ah[mf][3], uAh + addr);
                ldsm_x4_t(al[mf][0], al[mf][1], al[mf][2], al[mf][3], uAl + addr);
            }
            #pragma unroll
            for (int nb2 = 0; nb2 < 4; nb2++) {       // 4 groups of 16 a
                uint32_t addr = (b_row + nb2 * 16) * BPITCH + (s * 16 + b_k_off) * 2;
                uint32_t bh[4], bl[4];
                ldsm_x4(bh[0], bh[1], bh[2], bh[3], uBh + addr);
                ldsm_x4(bl[0], bl[1], bl[2], bl[3], uBl + addr);
                #pragma unroll
                for (int half = 0; half < 2; half++) {
                    int nb = nb2 * 2 + half;
                    #pragma unroll
                    for (int mf = 0; mf < 2; mf++) {
                        mma_bf16(acc[mf][nb], ah[mf], bh + half * 2);
                        mma_bf16(acc[mf][nb], al[mf], bh + half * 2);
                        mma_bf16(acc[mf][nb], ah[mf], bl + half * 2);
                    }
                }
            }
        }
        __syncthreads();
    }

    // ---- epilogue: h = tanh(acc + b1[a]); row-sum of W2[a]*h over a ----
    float rs[2][2] = {{0.f, 0.f}, {0.f, 0.f}};
    #pragma unroll
    for (int nb = 0; nb < 8; nb++) {
        int a0 = wn * 64 + nb * 8 + (lid & 3) * 2;
        float w20 = __ldg(&W2[a0]),   w21 = __ldg(&W2[a0 + 1]);
        float b10 = __ldg(&b1[a0]),   b11 = __ldg(&b1[a0 + 1]);
        #pragma unroll
        for (int mf = 0; mf < 2; mf++) {
            rs[mf][0] += w20 * fast_tanh(acc[mf][nb][0] + b10)
                       + w21 * fast_tanh(acc[mf][nb][1] + b11);
            rs[mf][1] += w20 * fast_tanh(acc[mf][nb][2] + b10)
                       + w21 * fast_tanh(acc[mf][nb][3] + b11);
        }
    }
    #pragma unroll
    for (int mf = 0; mf < 2; mf++)
        #pragma unroll
        for (int r = 0; r < 2; r++) {
            rs[mf][r] += __shfl_xor_sync(0xFFFFFFFF, rs[mf][r], 1);
            rs[mf][r] += __shfl_xor_sync(0xFFFFFFFF, rs[mf][r], 2);
        }
    if ((lid & 3) == 0) {
        int trow = wm * 32 + (lid >> 2);
        #pragma unroll
        for (int mf = 0; mf < 2; mf++) {
            red[wn][trow + mf * 16]     = rs[mf][0];
            red[wn][trow + mf * 16 + 8] = rs[mf][1];
        }
    }
    __syncthreads();
    if (tid < BM)
        g_logits[b * Tt + t0 + tid] = red[0][tid] + red[1][tid];
}

// ---------------- K3: per-batch max, exp, cumsum -> e, Z ----------------
__global__ __launch_bounds__(256) void k_softmax() {
    int b = blockIdx.x;
    __shared__ float sm[Tt];
    __shared__ float red[256];
    int tid = threadIdx.x;

    const float* lr = g_logits + b * Tt;
    float mx = -INFINITY;
    for (int j = tid; j < Tt; j += 256) { float v = lr[j]; sm[j] = v; mx = fmaxf(mx, v); }
    red[tid] = mx;
    __syncthreads();
    for (int off = 128; off; off >>= 1) {
        if (tid < off) red[tid] = fmaxf(red[tid], red[tid + off]);
        __syncthreads();
    }
    float M = red[0];
    __syncthreads();

    int base = tid * 16;
    float s = 0.f;
    #pragma unroll
    for (int k = 0; k < 16; k++) {
        float ev = expf(sm[base + k] - M);
        sm[base + k] = ev;
        s += ev;
    }
    red[tid] = s;
    __syncthreads();
    scan256(red, tid);

    float p = tid ? red[tid - 1] : 0.f;
    #pragma unroll
    for (int k = 0; k < 16; k++) {
        int t = base + k;
        float ev = sm[t];
        p += ev;
        g_e[b * Tt + t] = ev;
        g_Z[b * Tt + t] = p;
    }
}

// ---------------- K4: weighted mean/std scans + final reduction ----------------
__global__ __launch_bounds__(256) void k_weighted(const float* __restrict__ x,
                                                  float* __restrict__ out) {
    int row = blockIdx.x;
    int b = row / Cc;
    int c = row - b * Cc;

    __shared__ float xs[Tt];
    __shared__ float es[Tt];
    __shared__ float w1s[256], w2s[256];

    int tid = threadIdx.x;
    const float* xr = x + (size_t)row * Tt;
    const float* er = g_e + b * Tt;
    const float* zr = g_Z + b * Tt;
    for (int j = tid; j < Tt; j += 256) { xs[j] = xr[j]; es[j] = er[j]; }
    __syncthreads();

    int base = tid * 16;

    float s = 0.f;
    #pragma unroll
    for (int k = 0; k < 16; k++) { int t = base + k; s += es[t] * xs[t]; }
    w1s[tid] = s;
    __syncthreads();
    scan256(w1s, tid);

    float p = tid ? w1s[tid - 1] : 0.f;
    float sum_wm = 0.f, s2 = 0.f;
    #pragma unroll
    for (int k = 0; k < 16; k++) {
        int t = base + k;
        p += es[t] * xs[t];
        float wm = p / zr[t];
        sum_wm += wm;
        float d = xs[t] - wm;
        float v = es[t] * d * d;
        xs[t] = v;
        s2 += v;
    }
    __syncthreads();

    w1s[tid] = s2;
    __syncthreads();
    scan256(w1s, tid);

    float q = tid ? w1s[tid - 1] : 0.f;
    float sum_ws = 0.f;
    #pragma unroll
    for (int k = 0; k < 16; k++) {
        int t = base + k;
        q += xs[t];
        float wv = q / zr[t];
        sum_ws += sqrtf(fmaxf(wv, EPSF));
    }
    __syncthreads();

    w1s[tid] = sum_wm;
    w2s[tid] = sum_ws;
    __syncthreads();
    for (int off = 128; off; off >>= 1) {
        if (tid < off) { w1s[tid] += w1s[tid + off]; w2s[tid] += w2s[tid + off]; }
        __syncthreads();
    }
    if (tid == 0) {
        const float FW = (float)(1.0 / (4096.0 + 1e-12));
        out[(size_t)b * 2 * Cc + c]      = w1s[0] * FW;
        out[(size_t)b * 2 * Cc + Cc + c] = w2s[0] * FW;
    }
}

// ---------------- launch ----------------
extern "C" void kernel_launch(void* const* d_in, const int* in_sizes, int n_in,
                              void* d_out, int out_size) {
    (void)in_sizes; (void)n_in; (void)out_size;
    const float* x  = (const float*)d_in[0];
    const int*   L  = (const int*)  d_in[1];
    const float* W1 = (const float*)d_in[2];
    const float* b1 = (const float*)d_in[3];
    const float* W2 = (const float*)d_in[4];
    // d_in[5] = b2: constant shift on logits; cancels exactly in softmax.
    float* out = (float*)d_out;

    k_prepW<<<(Aa * K3C + 255) / 256, 256>>>(W1);
    k_scan_stats<<<Bb * Cc, 256>>>(x, L);
    dim3 g2(Tt / BM, Bb);
    k_gemm_mma<<<g2, 256>>>(x, b1, W2);
    k_softmax<<<Bb, 256>>>();
    k_weighted<<<Bb * Cc, 256>>>(x, out);
}